// round 10
// baseline (speedup 1.0000x reference)
#include <cuda_runtime.h>
#include <cuda_bf16.h>
#include <cstdint>

// Erosion2d: out[n,c,y,x] = 3x3 windowed min (pad 1e9) over (16,64,256,256) fp32.
// Separable min. One warp owns a full-width 256 x 64-row strip.
// R10: Blackwell 256-bit ops (ld.global.nc.v8 / st.global.cs.v8, 1KB/warp per
// instruction), 2 rotate shuffles per row, rolling register pipeline with
// prefetch depth 2. STRIPS=4 -> 512 blocks = single residency wave, halved halo.

#define EH 256
#define EW 256
#define STRIPS 4
#define ROWS_PER_STRIP (EH / STRIPS)

struct Row8 { float v[8]; };

__device__ __forceinline__ float fmin3(float a, float b, float c) {
    return fminf(a, fminf(b, c));
}

__device__ __forceinline__ Row8 inf_row() {
    const float inf = __int_as_float(0x7f800000);
    Row8 r;
#pragma unroll
    for (int i = 0; i < 8; ++i) r.v[i] = inf;
    return r;
}

__device__ __forceinline__ Row8 load_row(const float* __restrict__ src, int y,
                                         int off) {
    if ((unsigned)y < (unsigned)EH) {
        const float* p = src + (size_t)y * EW + off;
        Row8 r;
        asm volatile("ld.global.nc.v8.f32 {%0,%1,%2,%3,%4,%5,%6,%7}, [%8];"
                     : "=f"(r.v[0]), "=f"(r.v[1]), "=f"(r.v[2]), "=f"(r.v[3]),
                       "=f"(r.v[4]), "=f"(r.v[5]), "=f"(r.v[6]), "=f"(r.v[7])
                     : "l"(p));
        return r;
    }
    return inf_row();
}

__device__ __forceinline__ void store_row(float* __restrict__ dst, const Row8& r) {
    asm volatile("st.global.cs.v8.f32 [%0], {%1,%2,%3,%4,%5,%6,%7,%8};"
                 :: "l"(dst),
                    "f"(r.v[0]), "f"(r.v[1]), "f"(r.v[2]), "f"(r.v[3]),
                    "f"(r.v[4]), "f"(r.v[5]), "f"(r.v[6]), "f"(r.v[7])
                 : "memory");
}

// Horizontal 3-tap min. Lane l holds x=[8l,8l+8); neighbors via 2 rotate
// shuffles (lane l-1's elem7 = x=8l-1, lane l+1's elem0 = x=8l+8).
__device__ __forceinline__ Row8 hmin_row(const Row8& v, int lane) {
    const unsigned FULL = 0xffffffffu;
    const float inf = __int_as_float(0x7f800000);

    float lft = __shfl_sync(FULL, v.v[7], (lane + 31) & 31);
    float rgt = __shfl_sync(FULL, v.v[0], (lane + 1) & 31);
    if (lane == 0)  lft = inf;   // x = -1 padding
    if (lane == 31) rgt = inf;   // x = 256 padding

    Row8 h;
    h.v[0] = fmin3(lft, v.v[0], v.v[1]);
#pragma unroll
    for (int i = 1; i < 7; ++i)
        h.v[i] = fmin3(v.v[i - 1], v.v[i], v.v[i + 1]);
    h.v[7] = fmin3(v.v[6], v.v[7], rgt);
    return h;
}

__device__ __forceinline__ Row8 vmin3(const Row8& p, const Row8& q, const Row8& r) {
    Row8 o;
#pragma unroll
    for (int i = 0; i < 8; ++i)
        o.v[i] = fmin3(p.v[i], q.v[i], r.v[i]);
    return o;
}

__global__ __launch_bounds__(256, 4)
void Erosion2d_86517821212128_kernel(const float* __restrict__ x,
                                     float* __restrict__ out,
                                     int n_imgs) {
    const int gw    = (int)((blockIdx.x * blockDim.x + threadIdx.x) >> 5);
    const int lane  = (int)(threadIdx.x & 31);
    const int img   = gw >> 2;              // STRIPS = 4 warps/img
    const int strip = gw & (STRIPS - 1);
    if (img >= n_imgs) return;

    const float* src = x   + (size_t)img * (EH * EW);
    float*       dst = out + (size_t)img * (EH * EW);

    const int off = lane * 8;               // x in [8l, 8l+8)

    const int ys = strip * ROWS_PER_STRIP;

    // Pipeline: hA = hmin(y-1), hB = hmin(y); raw rows y+1 (rN), y+2 (rP).
    Row8 hA = hmin_row(load_row(src, ys - 1, off), lane);
    Row8 hB = hmin_row(load_row(src, ys,     off), lane);
    Row8 rN = load_row(src, ys + 1, off);
    Row8 rP = load_row(src, ys + 2, off);

#pragma unroll 2
    for (int yo = ys; yo < ys + ROWS_PER_STRIP; ++yo) {
        Row8 rQ = load_row(src, yo + 3, off);   // prefetch depth 2
        Row8 hC = hmin_row(rN, lane);
        Row8 o  = vmin3(hA, hB, hC);
        store_row(dst + (size_t)yo * EW + off, o);
        hA = hB;
        hB = hC;
        rN = rP;
        rP = rQ;
    }
}

extern "C" void kernel_launch(void* const* d_in, const int* in_sizes, int n_in,
                              void* d_out, int out_size) {
    const float* x = (const float*)d_in[0];
    float* out = (float*)d_out;
    const int n_imgs = in_sizes[0] / (EH * EW);          // 16*64 = 1024
    const int total_warps = n_imgs * STRIPS;             // 4096
    const int threads = 256;                             // 8 warps/block
    const int blocks = (total_warps * 32 + threads - 1) / threads;  // 512
    Erosion2d_86517821212128_kernel<<<blocks, threads>>>(x, out, n_imgs);
}

// round 11
// speedup vs baseline: 1.1136x; 1.1136x over previous
#include <cuda_runtime.h>
#include <cuda_bf16.h>
#include <cstdint>

// Erosion2d: out[n,c,y,x] = 3x3 windowed min (pad 1e9) over (16,64,256,256) fp32.
// Separable min. One warp owns a full-width 256 x 32-row strip.
// R11 = R9 (best ncu: 82us, 6226 GB/s) + non-coherent read path.
// Blackwell 256-bit ops: lane l holds 8 contiguous floats (x in [8l,8l+8)),
// one ld.global.nc.v8 + one st.global.cs.v8 per row (1KB/warp per instr).
// Horizontal 3-min: 2 rotate shuffles. Vertical 3-min: rolling register
// pipeline with prefetch-1. STRIPS=8 -> 8192 warps, 1024 blocks.

#define EH 256
#define EW 256
#define STRIPS 8
#define ROWS_PER_STRIP (EH / STRIPS)

struct Row8 { float v[8]; };

__device__ __forceinline__ float fmin3(float a, float b, float c) {
    return fminf(a, fminf(b, c));
}

__device__ __forceinline__ Row8 inf_row() {
    const float inf = __int_as_float(0x7f800000);
    Row8 r;
#pragma unroll
    for (int i = 0; i < 8; ++i) r.v[i] = inf;
    return r;
}

__device__ __forceinline__ Row8 load_row(const float* __restrict__ src, int y,
                                         int off) {
    if ((unsigned)y < (unsigned)EH) {
        const float* p = src + (size_t)y * EW + off;
        Row8 r;
        asm volatile("ld.global.nc.v8.f32 {%0,%1,%2,%3,%4,%5,%6,%7}, [%8];"
                     : "=f"(r.v[0]), "=f"(r.v[1]), "=f"(r.v[2]), "=f"(r.v[3]),
                       "=f"(r.v[4]), "=f"(r.v[5]), "=f"(r.v[6]), "=f"(r.v[7])
                     : "l"(p));
        return r;
    }
    return inf_row();
}

__device__ __forceinline__ void store_row(float* __restrict__ dst, const Row8& r) {
    asm volatile("st.global.cs.v8.f32 [%0], {%1,%2,%3,%4,%5,%6,%7,%8};"
                 :: "l"(dst),
                    "f"(r.v[0]), "f"(r.v[1]), "f"(r.v[2]), "f"(r.v[3]),
                    "f"(r.v[4]), "f"(r.v[5]), "f"(r.v[6]), "f"(r.v[7])
                 : "memory");
}

// Horizontal 3-tap min. Lane l holds x=[8l,8l+8); neighbors via 2 rotate
// shuffles (lane l-1's elem7 = x=8l-1, lane l+1's elem0 = x=8l+8).
__device__ __forceinline__ Row8 hmin_row(const Row8& v, int lane) {
    const unsigned FULL = 0xffffffffu;
    const float inf = __int_as_float(0x7f800000);

    float lft = __shfl_sync(FULL, v.v[7], (lane + 31) & 31);
    float rgt = __shfl_sync(FULL, v.v[0], (lane + 1) & 31);
    if (lane == 0)  lft = inf;   // x = -1 padding
    if (lane == 31) rgt = inf;   // x = 256 padding

    Row8 h;
    h.v[0] = fmin3(lft, v.v[0], v.v[1]);
#pragma unroll
    for (int i = 1; i < 7; ++i)
        h.v[i] = fmin3(v.v[i - 1], v.v[i], v.v[i + 1]);
    h.v[7] = fmin3(v.v[6], v.v[7], rgt);
    return h;
}

__device__ __forceinline__ Row8 vmin3(const Row8& p, const Row8& q, const Row8& r) {
    Row8 o;
#pragma unroll
    for (int i = 0; i < 8; ++i)
        o.v[i] = fmin3(p.v[i], q.v[i], r.v[i]);
    return o;
}

__global__ __launch_bounds__(256, 4)
void Erosion2d_86517821212128_kernel(const float* __restrict__ x,
                                     float* __restrict__ out,
                                     int n_imgs) {
    const int gw    = (int)((blockIdx.x * blockDim.x + threadIdx.x) >> 5);
    const int lane  = (int)(threadIdx.x & 31);
    const int img   = gw >> 3;              // STRIPS = 8 warps/img
    const int strip = gw & (STRIPS - 1);
    if (img >= n_imgs) return;

    const float* src = x   + (size_t)img * (EH * EW);
    float*       dst = out + (size_t)img * (EH * EW);

    const int off = lane * 8;               // x in [8l, 8l+8)

    const int ys = strip * ROWS_PER_STRIP;

    // Pipeline: hA = hmin(y-1), hB = hmin(y), rN = raw row y+1.
    Row8 hA = hmin_row(load_row(src, ys - 1, off), lane);
    Row8 hB = hmin_row(load_row(src, ys,     off), lane);
    Row8 rN = load_row(src, ys + 1, off);

#pragma unroll 2
    for (int yo = ys; yo < ys + ROWS_PER_STRIP; ++yo) {
        Row8 rP = load_row(src, yo + 2, off);   // prefetch next raw row
        Row8 hC = hmin_row(rN, lane);
        Row8 o  = vmin3(hA, hB, hC);
        store_row(dst + (size_t)yo * EW + off, o);
        hA = hB;
        hB = hC;
        rN = rP;
    }
}

extern "C" void kernel_launch(void* const* d_in, const int* in_sizes, int n_in,
                              void* d_out, int out_size) {
    const float* x = (const float*)d_in[0];
    float* out = (float*)d_out;
    const int n_imgs = in_sizes[0] / (EH * EW);          // 16*64 = 1024
    const int total_warps = n_imgs * STRIPS;             // 8192
    const int threads = 256;                             // 8 warps/block
    const int blocks = (total_warps * 32 + threads - 1) / threads;  // 1024
    Erosion2d_86517821212128_kernel<<<blocks, threads>>>(x, out, n_imgs);
}